// round 17
// baseline (speedup 1.0000x reference)
#include <cuda_runtime.h>
#include <cuda_fp16.h>

// LatentMap, R17: fused augmented-row table eliminates the positions scatter.
//
// Staged table (built per launch, 12.8MB): row p (128B, line-aligned) =
//   [ 32 x fp16 embedding (64B) | positions[p] float2 (8B) | pad (56B) ].
//
// Phase 1 (slimmed): lane l handles query qbase+l: coalesced position load,
//   floor, ONE scattered nbmap gather; stores nb + (fx,fy) to smem. No
//   position gathers, no sqrt here.
// Phase 2: per iteration, 4 queries; 8 lanes/query. Four LDG.128 per lane
//   (16B each, 8 lanes cover the full 128B row -> 4 full lines/instr)
//   deliver emb AND pos together. Lane f=4 of each query computes the 4
//   distances + normalized weights (f32, identical math to reference) and
//   broadcasts them with shfl.idx. Lanes f=0..3 blend 8 fp16 features each
//   and store two float4s (coalesced 128B/query total).
//
// Scattered-wavefront count/query drops 9 -> 5 (nbmap + 4 rows); the 4
// positions wavefronts ride inside the row gathers for free.
// fp16 embedding accuracy measured in R12: rel_err 2.08e-4 (< 1e-3).

#define IMG 1024
#define EMB 32
#define N_PTS_MAX 100000
#define ROW_BYTES 128
#define WPB 8
#define QPW 32

__device__ __align__(128) unsigned char g_table[(size_t)N_PTS_MAX * ROW_BYTES];

// ---------------------------------------------------------------- build table
__global__ void __launch_bounds__(256) build_table_kernel(
    const float*  __restrict__ embeddings,   // [n_pts, 32] f32
    const float2* __restrict__ positions,    // [n_pts]
    int n_pts)
{
    const int idx = blockIdx.x * blockDim.x + threadIdx.x;  // (p, f) pairs
    const int p = idx >> 3;
    const int f = idx & 7;
    if (p >= n_pts) return;

    // 4 f32 -> 4 fp16 (8B) at row offset f*8
    const float4 v = *(const float4*)&embeddings[p * EMB + f * 4];
    __half2 lo = __floats2half2_rn(v.x, v.y);
    __half2 hi = __floats2half2_rn(v.z, v.w);
    uint2 packed;
    packed.x = *(unsigned int*)&lo;
    packed.y = *(unsigned int*)&hi;
    *(uint2*)(g_table + (size_t)p * ROW_BYTES + f * 8) = packed;

    if (f == 0) {
        *(float2*)(g_table + (size_t)p * ROW_BYTES + 64) = positions[p];
    }
}

// ---------------------------------------------------------------- main
__global__ void __launch_bounds__(WPB * 32) latent_map_kernel(
    const float2* __restrict__ position,      // [N_Q]
    const int4*   __restrict__ neighbor_map,  // [IMG*IMG]
    const float*  __restrict__ harmonics,     // [EMB]
    float*        __restrict__ out,           // [N_Q, EMB]
    int n_q)
{
    __shared__ int4   s_nb[WPB][QPW];
    __shared__ float2 s_fp[WPB][QPW];

    const int warp = threadIdx.x >> 5;
    const int lane = threadIdx.x & 31;
    const int qbase = (blockIdx.x * WPB + warp) * QPW;
    const bool full_tile = (qbase + QPW) <= n_q;

    // ---- Phase 1 (slim): position + nbmap only ----
    {
        const int q = qbase + lane;
        if (full_tile || q < n_q) {
            const float2 p = position[q];
            const int ix = (int)floorf(p.x);
            const int iy = (int)floorf(p.y);
            s_nb[warp][lane] = neighbor_map[ix * IMG + iy];
            s_fp[warp][lane] = make_float2((float)ix, (float)iy);
        }
    }
    __syncwarp();

    // ---- Phase 2 ----
    const int sub = lane >> 3;          // query slot 0..3
    const int f   = lane & 7;           // 16B chunk within the 128B row
    const int src = (lane & 24) | 4;    // weight-owner lane of this sub

    // 8 harmonics for blending lanes (f<4); clamp index for f>=4 (unused).
    const int fh = (f & 3) * 8;
    const float4 ha = *(const float4*)&harmonics[fh];
    const float4 hb = *(const float4*)&harmonics[fh + 4];

    #pragma unroll
    for (int i = 0; i < QPW; i += 4) {
        const int ql = i + sub;
        const int q  = qbase + ql;
        const bool live = full_tile || (q < n_q);

        int4   nb = make_int4(0, 0, 0, 0);
        float2 fp = make_float2(0.f, 0.f);
        if (live) {
            nb = s_nb[warp][ql];     // broadcast LDS.128
            fp = s_fp[warp][ql];     // broadcast LDS.64
        }

        // Four full-line row gathers; lane f covers bytes [f*16, f*16+16).
        uint4 r0, r1, r2, r3;
        if (live) {
            r0 = *(const uint4*)(g_table + (size_t)nb.x * ROW_BYTES + f * 16);
            r1 = *(const uint4*)(g_table + (size_t)nb.y * ROW_BYTES + f * 16);
            r2 = *(const uint4*)(g_table + (size_t)nb.z * ROW_BYTES + f * 16);
            r3 = *(const uint4*)(g_table + (size_t)nb.w * ROW_BYTES + f * 16);
        } else {
            r0 = r1 = r2 = r3 = make_uint4(0, 0, 0, 0);
        }

        // Weight computation: meaningful only on lane f==4 (its 16B chunk
        // holds the row's float2 position). Other lanes compute garbage and
        // discard (no side effects).
        float w0, w1, w2, w3;
        {
            float dx, dy;
            dx = __uint_as_float(r0.x) - fp.x; dy = __uint_as_float(r0.y) - fp.y;
            const float d0 = sqrtf(dx * dx + dy * dy);
            dx = __uint_as_float(r1.x) - fp.x; dy = __uint_as_float(r1.y) - fp.y;
            const float d1 = sqrtf(dx * dx + dy * dy);
            dx = __uint_as_float(r2.x) - fp.x; dy = __uint_as_float(r2.y) - fp.y;
            const float d2 = sqrtf(dx * dx + dy * dy);
            dx = __uint_as_float(r3.x) - fp.x; dy = __uint_as_float(r3.y) - fp.y;
            const float d3 = sqrtf(dx * dx + dy * dy);

            const float rs = 1.0f / (d0 + d1 + d2 + d3 + 1e-8f);
            w0 = 1.0f - d0 * rs;
            w1 = 1.0f - d1 * rs;
            w2 = 1.0f - d2 * rs;
            w3 = 1.0f - d3 * rs;
        }
        // Broadcast the weights from each query's lane f==4.
        w0 = __shfl_sync(0xffffffffu, w0, src);
        w1 = __shfl_sync(0xffffffffu, w1, src);
        w2 = __shfl_sync(0xffffffffu, w2, src);
        w3 = __shfl_sync(0xffffffffu, w3, src);

        // Blend 8 features on lanes f<4 (each holds features fh..fh+8).
        if (f < 4 && live) {
            const __half2* h0 = (const __half2*)&r0;
            const __half2* h1 = (const __half2*)&r1;
            const __half2* h2 = (const __half2*)&r2;
            const __half2* h3 = (const __half2*)&r3;

            float acc[8];
            #pragma unroll
            for (int m = 0; m < 4; ++m) {
                const float2 e0 = __half22float2(h0[m]);
                const float2 e1 = __half22float2(h1[m]);
                const float2 e2 = __half22float2(h2[m]);
                const float2 e3 = __half22float2(h3[m]);
                acc[m * 2]     = w0 * e0.x + w1 * e1.x + w2 * e2.x + w3 * e3.x;
                acc[m * 2 + 1] = w0 * e0.y + w1 * e1.y + w2 * e2.y + w3 * e3.y;
            }

            float4 oa, ob;
            oa.x = acc[0] * ha.x; oa.y = acc[1] * ha.y;
            oa.z = acc[2] * ha.z; oa.w = acc[3] * ha.w;
            ob.x = acc[4] * hb.x; ob.y = acc[5] * hb.y;
            ob.z = acc[6] * hb.z; ob.w = acc[7] * hb.w;

            float* dst = &out[(long)q * EMB + fh];
            *(float4*)dst       = oa;
            *(float4*)(dst + 4) = ob;
        }
    }
}

extern "C" void kernel_launch(void* const* d_in, const int* in_sizes, int n_in,
                              void* d_out, int out_size)
{
    const float2* position     = (const float2*)d_in[0];
    const float2* positions    = (const float2*)d_in[1];
    const int4*   neighbor_map = (const int4*)d_in[2];
    const float*  embeddings   = (const float*)d_in[3];
    const float*  harmonics    = (const float*)d_in[4];
    float*        out          = (float*)d_out;

    const int n_q = in_sizes[0] / 2;
    int n_pts = in_sizes[3] / EMB;
    if (n_pts > N_PTS_MAX) n_pts = N_PTS_MAX;

    // Kernel 0: build the augmented fp16+pos table.
    {
        const int threads = n_pts * 8;
        const int block = 256;
        const int grid = (threads + block - 1) / block;
        build_table_kernel<<<grid, block>>>(embeddings, positions, n_pts);
    }

    // Kernel 1: fused main kernel.
    {
        const int queries_per_block = WPB * QPW;  // 256
        const int grid = (n_q + queries_per_block - 1) / queries_per_block;
        latent_map_kernel<<<grid, WPB * 32>>>(
            position, neighbor_map, harmonics, out, n_q);
    }
}